// round 1
// baseline (speedup 1.0000x reference)
#include <cuda_runtime.h>
#include <math.h>

// ---------------- problem constants ----------------
#define BATCH   4
#define CDIM    512
#define HSZ     64
#define WSZ_    64
#define HW      4096            // 64*64
#define TTOK    16384           // BATCH*HW
#define HEADDIM 64
#define NHEADS_H 4
#define NHEADS_L 4
#define HDIM    256             // NHEADS_H * HEADDIM
#define LDIM    256
#define GWIN    1024            // 32*32 windows per batch
#define SCALE   0.125f          // 64^-0.5

// ---------------- scratch (device globals; allocation-free) ----------------
__device__ float g_xt[TTOK * CDIM];          // x transposed: [t][c]
__device__ float g_pooled[BATCH * GWIN * CDIM];
__device__ float g_qkv[TTOK * 3 * HDIM];     // [t][768]
__device__ float g_hout[TTOK * HDIM];
__device__ float g_hifi[TTOK * HDIM];
__device__ float g_lq[TTOK * LDIM];
__device__ float g_kv[BATCH * GWIN * 2 * LDIM];
__device__ float g_lo[TTOK * LDIM];
__device__ float g_lofi[TTOK * LDIM];

// ---------------- 1) transpose x (B,C,H,W) -> xt [t][c] ----------------
__global__ void transpose_x_kernel(const float* __restrict__ x, float* __restrict__ xt) {
    __shared__ float tile[32][33];
    int hw0 = blockIdx.x * 32;
    int c0  = blockIdx.y * 32;
    int b   = blockIdx.z;
    int tx = threadIdx.x, ty = threadIdx.y;
#pragma unroll
    for (int i = 0; i < 4; i++) {
        tile[ty + i * 8][tx] = x[((size_t)(b * CDIM + c0 + ty + i * 8)) * HW + hw0 + tx];
    }
    __syncthreads();
#pragma unroll
    for (int i = 0; i < 4; i++) {
        xt[((size_t)(b * HW + hw0 + ty + i * 8)) * CDIM + c0 + tx] = tile[tx][ty + i * 8];
    }
}

// ---------------- 2) 2x2 average pool (from xt) ----------------
__global__ void pool_kernel(const float* __restrict__ xt, float* __restrict__ pooled) {
    int bg = blockIdx.x;               // b*1024 + gy*32 + gx
    int b = bg >> 10;
    int g = bg & 1023;
    int gy = g >> 5, gx = g & 31;
    int t00 = b * HW + (gy * 2) * WSZ_ + gx * 2;
    const float* r0 = xt + (size_t)t00 * CDIM;
    const float* r1 = xt + (size_t)(t00 + 1) * CDIM;
    const float* r2 = xt + (size_t)(t00 + WSZ_) * CDIM;
    const float* r3 = xt + (size_t)(t00 + WSZ_ + 1) * CDIM;
    float* dst = pooled + (size_t)bg * CDIM;
    for (int c = threadIdx.x; c < CDIM; c += 128) {
        dst[c] = 0.25f * (r0[c] + r1[c] + r2[c] + r3[c]);
    }
}

// ---------------- generic SGEMM: C[M,N] = A[M,K] @ B[K,N] (+bias) ----------------
// BM=BN=64, BK=16, 256 threads, 4x4 microtile. All dims divide tiles exactly.
template <bool HAS_BIAS>
__global__ void sgemm_kernel(const float* __restrict__ A, const float* __restrict__ B,
                             const float* __restrict__ bias, float* __restrict__ C,
                             int M, int N, int K) {
    __shared__ float As[16][64];
    __shared__ float Bs[16][64];
    int tid = threadIdx.x;
    int tx = tid & 15, ty = tid >> 4;
    int m0 = blockIdx.y * 64, n0 = blockIdx.x * 64;

    int aRow = tid >> 2;           // 0..63
    int aCol = (tid & 3) * 4;      // 0..12
    int bRow = tid >> 4;           // 0..15
    int bCol = (tid & 15) * 4;     // 0..60

    float acc[4][4];
#pragma unroll
    for (int i = 0; i < 4; i++)
#pragma unroll
        for (int j = 0; j < 4; j++) acc[i][j] = 0.f;

    for (int k0 = 0; k0 < K; k0 += 16) {
        float4 a = *(const float4*)&A[(size_t)(m0 + aRow) * K + k0 + aCol];
        As[aCol + 0][aRow] = a.x;
        As[aCol + 1][aRow] = a.y;
        As[aCol + 2][aRow] = a.z;
        As[aCol + 3][aRow] = a.w;
        *(float4*)&Bs[bRow][bCol] = *(const float4*)&B[(size_t)(k0 + bRow) * N + n0 + bCol];
        __syncthreads();
#pragma unroll
        for (int k = 0; k < 16; k++) {
            float4 ra = *(const float4*)&As[k][ty * 4];
            float4 rb = *(const float4*)&Bs[k][tx * 4];
            acc[0][0] += ra.x * rb.x; acc[0][1] += ra.x * rb.y; acc[0][2] += ra.x * rb.z; acc[0][3] += ra.x * rb.w;
            acc[1][0] += ra.y * rb.x; acc[1][1] += ra.y * rb.y; acc[1][2] += ra.y * rb.z; acc[1][3] += ra.y * rb.w;
            acc[2][0] += ra.z * rb.x; acc[2][1] += ra.z * rb.y; acc[2][2] += ra.z * rb.z; acc[2][3] += ra.z * rb.w;
            acc[3][0] += ra.w * rb.x; acc[3][1] += ra.w * rb.y; acc[3][2] += ra.w * rb.z; acc[3][3] += ra.w * rb.w;
        }
        __syncthreads();
    }

    float4 bv = make_float4(0.f, 0.f, 0.f, 0.f);
    if (HAS_BIAS) bv = *(const float4*)&bias[n0 + tx * 4];
#pragma unroll
    for (int i = 0; i < 4; i++) {
        float4 out;
        out.x = acc[i][0] + bv.x;
        out.y = acc[i][1] + bv.y;
        out.z = acc[i][2] + bv.z;
        out.w = acc[i][3] + bv.w;
        *(float4*)&C[(size_t)(m0 + ty * 4 + i) * N + n0 + tx * 4] = out;
    }
}

// ---------------- 3) window attention (2x2 windows, warp per head) ----------------
__global__ void winattn_kernel(const float* __restrict__ qkv, float* __restrict__ hout) {
    int win = blockIdx.x;          // 0..4095
    int b = win >> 10;
    int g = win & 1023;
    int gy = g >> 5, gx = g & 31;
    int head = threadIdx.x >> 5;
    int lane = threadIdx.x & 31;

    int tbase = b * HW + gy * 2 * WSZ_ + gx * 2;
    int t[4] = {tbase, tbase + 1, tbase + WSZ_, tbase + WSZ_ + 1};

    float q[4][2], k[4][2], v[4][2];
#pragma unroll
    for (int n = 0; n < 4; n++) {
        const float* row = qkv + (size_t)t[n] * (3 * HDIM) + head * HEADDIM + lane;
        q[n][0] = row[0];          q[n][1] = row[32];
        k[n][0] = row[HDIM];       k[n][1] = row[HDIM + 32];
        v[n][0] = row[2 * HDIM];   v[n][1] = row[2 * HDIM + 32];
    }

    float s[4][4];
#pragma unroll
    for (int n = 0; n < 4; n++)
#pragma unroll
        for (int m = 0; m < 4; m++) s[n][m] = q[n][0] * k[m][0] + q[n][1] * k[m][1];

#pragma unroll
    for (int o = 16; o > 0; o >>= 1)
#pragma unroll
        for (int n = 0; n < 4; n++)
#pragma unroll
            for (int m = 0; m < 4; m++) s[n][m] += __shfl_xor_sync(0xffffffffu, s[n][m], o);

#pragma unroll
    for (int n = 0; n < 4; n++) {
        float sv[4];
#pragma unroll
        for (int m = 0; m < 4; m++) sv[m] = s[n][m] * SCALE;
        float mx = fmaxf(fmaxf(sv[0], sv[1]), fmaxf(sv[2], sv[3]));
        float p[4], l = 0.f;
#pragma unroll
        for (int m = 0; m < 4; m++) { p[m] = __expf(sv[m] - mx); l += p[m]; }
        float inv = 1.f / l;
        float o0 = 0.f, o1 = 0.f;
#pragma unroll
        for (int m = 0; m < 4; m++) { o0 += p[m] * v[m][0]; o1 += p[m] * v[m][1]; }
        float* dst = hout + (size_t)t[n] * HDIM + head * HEADDIM + lane;
        dst[0]  = o0 * inv;
        dst[32] = o1 * inv;
    }
}

// ---------------- 4) low-freq attention (flash-style) ----------------
// grid: (4096/64 per batch, B*NHEADS_L), block 256, dyn smem = 66048 B
__global__ void lowattn_kernel(const float* __restrict__ lq, const float* __restrict__ kv,
                               float* __restrict__ lo) {
    extern __shared__ float sm[];
    float* Qt = sm;                 // [64 d][65]
    float* Kt = Qt + 64 * 65;       // [64 d][65]
    float* Vs = Kt + 64 * 65;       // [64 key][64 d]
    float* Ps = Vs + 64 * 64;       // [64 q][64 key]

    int qtile = blockIdx.x;         // 0..63
    int bh = blockIdx.y;            // 0..15
    int b = bh >> 2, head = bh & 3;
    int q0 = qtile * 64;
    int tid = threadIdx.x;
    int tx = tid & 15, ty = tid >> 4;

    for (int idx = tid; idx < 64 * 64; idx += 256) {
        int r = idx >> 6, d = idx & 63;
        Qt[d * 65 + r] = lq[(size_t)(b * HW + q0 + r) * LDIM + head * HEADDIM + d];
    }

    float m_i[4], l_i[4], O[4][4];
#pragma unroll
    for (int i = 0; i < 4; i++) {
        m_i[i] = -1e30f; l_i[i] = 0.f;
#pragma unroll
        for (int j = 0; j < 4; j++) O[i][j] = 0.f;
    }
    __syncthreads();

    for (int kc = 0; kc < GWIN; kc += 64) {
        if (kc) __syncthreads();   // previous P@V done before reloading K/V
        for (int idx = tid; idx < 64 * 64; idx += 256) {
            int r = idx >> 6, d = idx & 63;
            const float* src = kv + (size_t)(b * GWIN + kc + r) * (2 * LDIM) + head * HEADDIM + d;
            Kt[d * 65 + r] = src[0];
            Vs[r * 64 + d] = src[LDIM];
        }
        __syncthreads();

        float s[4][4];
#pragma unroll
        for (int i = 0; i < 4; i++)
#pragma unroll
            for (int j = 0; j < 4; j++) s[i][j] = 0.f;

        for (int d = 0; d < 64; d++) {
            float qa[4], kb[4];
#pragma unroll
            for (int i = 0; i < 4; i++) qa[i] = Qt[d * 65 + ty * 4 + i];
#pragma unroll
            for (int j = 0; j < 4; j++) kb[j] = Kt[d * 65 + tx * 4 + j];
#pragma unroll
            for (int i = 0; i < 4; i++)
#pragma unroll
                for (int j = 0; j < 4; j++) s[i][j] += qa[i] * kb[j];
        }

#pragma unroll
        for (int i = 0; i < 4; i++) {
            float sv[4];
#pragma unroll
            for (int j = 0; j < 4; j++) sv[j] = s[i][j] * SCALE;
            float mx = fmaxf(fmaxf(sv[0], sv[1]), fmaxf(sv[2], sv[3]));
#pragma unroll
            for (int o = 8; o > 0; o >>= 1) mx = fmaxf(mx, __shfl_xor_sync(0xffffffffu, mx, o, 16));
            float mnew = fmaxf(m_i[i], mx);
            float p[4], rs = 0.f;
#pragma unroll
            for (int j = 0; j < 4; j++) { p[j] = __expf(sv[j] - mnew); rs += p[j]; }
#pragma unroll
            for (int o = 8; o > 0; o >>= 1) rs += __shfl_xor_sync(0xffffffffu, rs, o, 16);
            float alpha = __expf(m_i[i] - mnew);
            l_i[i] = l_i[i] * alpha + rs;
            m_i[i] = mnew;
#pragma unroll
            for (int j = 0; j < 4; j++) O[i][j] *= alpha;
#pragma unroll
            for (int j = 0; j < 4; j++) Ps[(ty * 4 + i) * 64 + tx * 4 + j] = p[j];
        }
        __syncthreads();

        for (int c = 0; c < 64; c++) {
            float pv[4], vv[4];
#pragma unroll
            for (int i = 0; i < 4; i++) pv[i] = Ps[(ty * 4 + i) * 64 + c];
#pragma unroll
            for (int j = 0; j < 4; j++) vv[j] = Vs[c * 64 + tx * 4 + j];
#pragma unroll
            for (int i = 0; i < 4; i++)
#pragma unroll
                for (int j = 0; j < 4; j++) O[i][j] += pv[i] * vv[j];
        }
    }

#pragma unroll
    for (int i = 0; i < 4; i++) {
        float inv = 1.f / l_i[i];
#pragma unroll
        for (int j = 0; j < 4; j++) {
            lo[(size_t)(b * HW + q0 + ty * 4 + i) * LDIM + head * HEADDIM + tx * 4 + j] = O[i][j] * inv;
        }
    }
}

// ---------------- 5) pack: [t][256] x2 -> out (B, 512, H, W) ----------------
__global__ void pack_kernel(const float* __restrict__ hifi, const float* __restrict__ lofi,
                            float* __restrict__ out) {
    __shared__ float tile[32][33];
    int t0 = blockIdx.x * 32;
    int c0g = blockIdx.y * 32;
    int tx = threadIdx.x, ty = threadIdx.y;
    const float* src;
    int c0;
    if (c0g < HDIM) { src = hifi; c0 = c0g; } else { src = lofi; c0 = c0g - HDIM; }
#pragma unroll
    for (int i = 0; i < 4; i++) {
        tile[ty + i * 8][tx] = src[(size_t)(t0 + ty + i * 8) * 256 + c0 + tx];
    }
    __syncthreads();
    int b = t0 / HW;
    int hw0 = t0 % HW;
#pragma unroll
    for (int i = 0; i < 4; i++) {
        out[(size_t)(b * CDIM + c0g + ty + i * 8) * HW + hw0 + tx] = tile[tx][ty + i * 8];
    }
}

// ---------------- launch ----------------
extern "C" void kernel_launch(void* const* d_in, const int* in_sizes, int n_in,
                              void* d_out, int out_size) {
    const float* x        = (const float*)d_in[0];
    const float* h_qkv_w  = (const float*)d_in[1];
    const float* h_proj_w = (const float*)d_in[2];
    const float* h_proj_b = (const float*)d_in[3];
    const float* l_q_w    = (const float*)d_in[4];
    const float* l_kv_w   = (const float*)d_in[5];
    const float* l_proj_w = (const float*)d_in[6];
    const float* l_proj_b = (const float*)d_in[7];
    float* out = (float*)d_out;

    float *p_xt, *p_pooled, *p_qkv, *p_hout, *p_hifi, *p_lq, *p_kv, *p_lo, *p_lofi;
    cudaGetSymbolAddress((void**)&p_xt, g_xt);
    cudaGetSymbolAddress((void**)&p_pooled, g_pooled);
    cudaGetSymbolAddress((void**)&p_qkv, g_qkv);
    cudaGetSymbolAddress((void**)&p_hout, g_hout);
    cudaGetSymbolAddress((void**)&p_hifi, g_hifi);
    cudaGetSymbolAddress((void**)&p_lq, g_lq);
    cudaGetSymbolAddress((void**)&p_kv, g_kv);
    cudaGetSymbolAddress((void**)&p_lo, g_lo);
    cudaGetSymbolAddress((void**)&p_lofi, g_lofi);

    // 1) transpose
    transpose_x_kernel<<<dim3(HW / 32, CDIM / 32, BATCH), dim3(32, 8)>>>(x, p_xt);
    // 2) pool
    pool_kernel<<<BATCH * GWIN, 128>>>(p_xt, p_pooled);
    // 3) qkv = xt @ h_qkv_w   [16384 x 768], K=512
    sgemm_kernel<false><<<dim3(768 / 64, TTOK / 64), 256>>>(p_xt, h_qkv_w, nullptr, p_qkv, TTOK, 768, CDIM);
    // 4) window attention
    winattn_kernel<<<BATCH * GWIN, 128>>>(p_qkv, p_hout);
    // 5) hifi = hout @ h_proj_w + b  [16384 x 256], K=256
    sgemm_kernel<true><<<dim3(HDIM / 64, TTOK / 64), 256>>>(p_hout, h_proj_w, h_proj_b, p_hifi, TTOK, HDIM, HDIM);
    // 6) lq = xt @ l_q_w  [16384 x 256], K=512
    sgemm_kernel<false><<<dim3(LDIM / 64, TTOK / 64), 256>>>(p_xt, l_q_w, nullptr, p_lq, TTOK, LDIM, CDIM);
    // 7) kv = pooled @ l_kv_w  [4096 x 512], K=512
    sgemm_kernel<false><<<dim3(512 / 64, (BATCH * GWIN) / 64), 256>>>(p_pooled, l_kv_w, nullptr, p_kv,
                                                                     BATCH * GWIN, 2 * LDIM, CDIM);
    // 8) low attention
    size_t la_smem = (size_t)(64 * 65 * 2 + 64 * 64 * 2) * sizeof(float);  // 66048 B
    cudaFuncSetAttribute(lowattn_kernel, cudaFuncAttributeMaxDynamicSharedMemorySize, (int)la_smem);
    lowattn_kernel<<<dim3(HW / 64, BATCH * NHEADS_L), 256, la_smem>>>(p_lq, p_kv, p_lo);
    // 9) lofi = lo @ l_proj_w + b
    sgemm_kernel<true><<<dim3(LDIM / 64, TTOK / 64), 256>>>(p_lo, l_proj_w, l_proj_b, p_lofi, TTOK, LDIM, LDIM);
    // 10) pack to (B, 512, H, W)
    pack_kernel<<<dim3(TTOK / 32, CDIM / 32), dim3(32, 8)>>>(p_hifi, p_lofi, out);
}

// round 2
// speedup vs baseline: 2.9854x; 2.9854x over previous
#include <cuda_runtime.h>
#include <math.h>
#include <stdint.h>

// ---------------- problem constants ----------------
#define BATCH   4
#define CDIM    512
#define WSZ_    64
#define HW      4096            // 64*64
#define TTOK    16384           // BATCH*HW
#define HEADDIM 64
#define HDIM    256
#define LDIM    256
#define GWIN    1024            // pooled tokens per batch
#define SCALE   0.125f

// ---------------- scratch ----------------
__device__ float g_xt[TTOK * CDIM];
__device__ float g_pooled[BATCH * GWIN * CDIM];
__device__ float g_qkv[TTOK * 3 * HDIM];
__device__ float g_hout[TTOK * HDIM];
__device__ float g_hifi[TTOK * HDIM];
__device__ float g_lq[TTOK * LDIM];
__device__ float g_kv[BATCH * GWIN * 2 * LDIM];
__device__ float g_lo[TTOK * LDIM];
__device__ float g_lofi[TTOK * LDIM];

__device__ __forceinline__ uint32_t f2tf32(float x) {
    uint32_t r;
    asm("cvt.rna.tf32.f32 %0, %1;" : "=r"(r) : "f"(x));
    return r;
}

__device__ __forceinline__ void mma_tf32(float c[4], const uint32_t a[4], const uint32_t b[2]) {
    asm volatile(
        "mma.sync.aligned.m16n8k8.row.col.f32.tf32.tf32.f32 "
        "{%0,%1,%2,%3}, {%4,%5,%6,%7}, {%8,%9}, {%0,%1,%2,%3};\n"
        : "+f"(c[0]), "+f"(c[1]), "+f"(c[2]), "+f"(c[3])
        : "r"(a[0]), "r"(a[1]), "r"(a[2]), "r"(a[3]), "r"(b[0]), "r"(b[1]));
}

// ---------------- 1) transpose x (B,C,H,W) -> xt [t][c] ----------------
__global__ void transpose_x_kernel(const float* __restrict__ x, float* __restrict__ xt) {
    __shared__ float tile[32][33];
    int hw0 = blockIdx.x * 32;
    int c0  = blockIdx.y * 32;
    int b   = blockIdx.z;
    int tx = threadIdx.x, ty = threadIdx.y;
#pragma unroll
    for (int i = 0; i < 4; i++)
        tile[ty + i * 8][tx] = x[((size_t)(b * CDIM + c0 + ty + i * 8)) * HW + hw0 + tx];
    __syncthreads();
#pragma unroll
    for (int i = 0; i < 4; i++)
        xt[((size_t)(b * HW + hw0 + ty + i * 8)) * CDIM + c0 + tx] = tile[tx][ty + i * 8];
}

// ---------------- 2) 2x2 average pool ----------------
__global__ void pool_kernel(const float* __restrict__ xt, float* __restrict__ pooled) {
    int bg = blockIdx.x;
    int b = bg >> 10;
    int g = bg & 1023;
    int gy = g >> 5, gx = g & 31;
    int t00 = b * HW + (gy * 2) * WSZ_ + gx * 2;
    const float* r0 = xt + (size_t)t00 * CDIM;
    const float* r1 = xt + (size_t)(t00 + 1) * CDIM;
    const float* r2 = xt + (size_t)(t00 + WSZ_) * CDIM;
    const float* r3 = xt + (size_t)(t00 + WSZ_ + 1) * CDIM;
    float* dst = pooled + (size_t)bg * CDIM;
    for (int c = threadIdx.x; c < CDIM; c += 128)
        dst[c] = 0.25f * (r0[c] + r1[c] + r2[c] + r3[c]);
}

// ---------------- tf32 tensor-core GEMM: C = A[M,K] @ B[K,N] (+bias) ----------------
// Block 256 thr (8 warps, 2x4), tile 128x128x32, warp tile 64x32.
template <bool HAS_BIAS>
__global__ void __launch_bounds__(256) tf32_gemm(const float* __restrict__ A,
                                                 const float* __restrict__ B,
                                                 const float* __restrict__ bias,
                                                 float* __restrict__ C,
                                                 int M, int N, int K) {
    __shared__ float As[128 * 36];   // [m][k], pad 36
    __shared__ float Bs[32 * 136];   // [k][n], pad 136
    const uint32_t* Asu = (const uint32_t*)As;
    const uint32_t* Bsu = (const uint32_t*)Bs;

    int tid = threadIdx.x;
    int warp = tid >> 5, lane = tid & 31;
    int g = lane >> 2, tig = lane & 3;
    int mw = (warp & 1) * 64;   // warp m offset in tile
    int nw = (warp >> 1) * 32;  // warp n offset in tile
    int m0 = blockIdx.y * 128, n0 = blockIdx.x * 128;

    float acc[4][4][4];
#pragma unroll
    for (int mt = 0; mt < 4; mt++)
#pragma unroll
        for (int nt = 0; nt < 4; nt++)
#pragma unroll
            for (int j = 0; j < 4; j++) acc[mt][nt][j] = 0.f;

    for (int k0 = 0; k0 < K; k0 += 32) {
        if (k0) __syncthreads();
#pragma unroll
        for (int i = 0; i < 4; i++) {
            int lin = tid + i * 256;            // float4 index
            int r = lin >> 3, c4 = (lin & 7) * 4;
            float4 v = *(const float4*)&A[(size_t)(m0 + r) * K + k0 + c4];
            uint4 t;
            t.x = f2tf32(v.x); t.y = f2tf32(v.y); t.z = f2tf32(v.z); t.w = f2tf32(v.w);
            *(uint4*)&As[r * 36 + c4] = t;
            int rb = lin >> 5, cb4 = (lin & 31) * 4;
            float4 w = *(const float4*)&B[(size_t)(k0 + rb) * N + n0 + cb4];
            uint4 t2;
            t2.x = f2tf32(w.x); t2.y = f2tf32(w.y); t2.z = f2tf32(w.z); t2.w = f2tf32(w.w);
            *(uint4*)&Bs[rb * 136 + cb4] = t2;
        }
        __syncthreads();

#pragma unroll
        for (int k8 = 0; k8 < 4; k8++) {
            uint32_t af[4][4];
#pragma unroll
            for (int mt = 0; mt < 4; mt++) {
                int r = mw + mt * 16 + g;
                af[mt][0] = Asu[r * 36 + k8 * 8 + tig];
                af[mt][1] = Asu[(r + 8) * 36 + k8 * 8 + tig];
                af[mt][2] = Asu[r * 36 + k8 * 8 + tig + 4];
                af[mt][3] = Asu[(r + 8) * 36 + k8 * 8 + tig + 4];
            }
            uint32_t bf[4][2];
#pragma unroll
            for (int nt = 0; nt < 4; nt++) {
                int c = nw + nt * 8 + g;
                bf[nt][0] = Bsu[(k8 * 8 + tig) * 136 + c];
                bf[nt][1] = Bsu[(k8 * 8 + tig + 4) * 136 + c];
            }
#pragma unroll
            for (int mt = 0; mt < 4; mt++)
#pragma unroll
                for (int nt = 0; nt < 4; nt++)
                    mma_tf32(acc[mt][nt], af[mt], bf[nt]);
        }
    }

#pragma unroll
    for (int mt = 0; mt < 4; mt++) {
        int r = m0 + mw + mt * 16 + g;
#pragma unroll
        for (int nt = 0; nt < 4; nt++) {
            int c = n0 + nw + nt * 8 + tig * 2;
            float bx = 0.f, by = 0.f;
            if (HAS_BIAS) { bx = bias[c]; by = bias[c + 1]; }
            float2 o0, o1;
            o0.x = acc[mt][nt][0] + bx; o0.y = acc[mt][nt][1] + by;
            o1.x = acc[mt][nt][2] + bx; o1.y = acc[mt][nt][3] + by;
            *(float2*)&C[(size_t)r * N + c] = o0;
            *(float2*)&C[(size_t)(r + 8) * N + c] = o1;
        }
    }
}

// ---------------- 3) window attention (2x2 windows, warp per head) ----------------
__global__ void winattn_kernel(const float* __restrict__ qkv, float* __restrict__ hout) {
    int win = blockIdx.x;
    int b = win >> 10;
    int g = win & 1023;
    int gy = g >> 5, gx = g & 31;
    int head = threadIdx.x >> 5;
    int lane = threadIdx.x & 31;

    int tbase = b * HW + gy * 2 * WSZ_ + gx * 2;
    int t[4] = {tbase, tbase + 1, tbase + WSZ_, tbase + WSZ_ + 1};

    float q[4][2], k[4][2], v[4][2];
#pragma unroll
    for (int n = 0; n < 4; n++) {
        const float* row = qkv + (size_t)t[n] * (3 * HDIM) + head * HEADDIM + lane;
        q[n][0] = row[0];          q[n][1] = row[32];
        k[n][0] = row[HDIM];       k[n][1] = row[HDIM + 32];
        v[n][0] = row[2 * HDIM];   v[n][1] = row[2 * HDIM + 32];
    }

    float s[4][4];
#pragma unroll
    for (int n = 0; n < 4; n++)
#pragma unroll
        for (int m = 0; m < 4; m++) s[n][m] = q[n][0] * k[m][0] + q[n][1] * k[m][1];

#pragma unroll
    for (int o = 16; o > 0; o >>= 1)
#pragma unroll
        for (int n = 0; n < 4; n++)
#pragma unroll
            for (int m = 0; m < 4; m++) s[n][m] += __shfl_xor_sync(0xffffffffu, s[n][m], o);

#pragma unroll
    for (int n = 0; n < 4; n++) {
        float sv[4];
#pragma unroll
        for (int m = 0; m < 4; m++) sv[m] = s[n][m] * SCALE;
        float mx = fmaxf(fmaxf(sv[0], sv[1]), fmaxf(sv[2], sv[3]));
        float p[4], l = 0.f;
#pragma unroll
        for (int m = 0; m < 4; m++) { p[m] = __expf(sv[m] - mx); l += p[m]; }
        float inv = 1.f / l;
        float o0 = 0.f, o1 = 0.f;
#pragma unroll
        for (int m = 0; m < 4; m++) { o0 += p[m] * v[m][0]; o1 += p[m] * v[m][1]; }
        float* dst = hout + (size_t)t[n] * HDIM + head * HEADDIM + lane;
        dst[0]  = o0 * inv;
        dst[32] = o1 * inv;
    }
}

// ---------------- 4) low-freq flash attention with tf32 mma ----------------
// grid (64 qtiles, B*4 heads), block 128 (4 warps). Each warp: 16 q rows.
// dyn smem: Qs 64x68 | Ks 64x68 | Vs 64x72 | Ps 64x68 = 70656 B
#define LA_Q  0
#define LA_K  (64 * 68)
#define LA_V  (LA_K + 64 * 68)
#define LA_P  (LA_V + 64 * 72)
#define LA_FLOATS (LA_P + 64 * 68)

__global__ void __launch_bounds__(128) lowattn_mma_kernel(const float* __restrict__ lq,
                                                          const float* __restrict__ kv,
                                                          float* __restrict__ lo) {
    extern __shared__ float sm[];
    uint32_t* smu = (uint32_t*)sm;

    int qtile = blockIdx.x;
    int bh = blockIdx.y;
    int b = bh >> 2, head = bh & 3;
    int q0 = qtile * 64;
    int tid = threadIdx.x;
    int warp = tid >> 5, lane = tid & 31;
    int g = lane >> 2, tig = lane & 3;
    int rbase = warp * 16;

    // load Q tile (64x64) with tf32 cvt
#pragma unroll
    for (int i = 0; i < 8; i++) {
        int lin = tid + i * 128;          // float4 idx
        int r = lin >> 4, c4 = (lin & 15) * 4;
        float4 v = *(const float4*)&lq[(size_t)(b * HW + q0 + r) * LDIM + head * HEADDIM + c4];
        uint4 t;
        t.x = f2tf32(v.x); t.y = f2tf32(v.y); t.z = f2tf32(v.z); t.w = f2tf32(v.w);
        *(uint4*)&sm[LA_Q + r * 68 + c4] = t;
    }

    float m0 = -1e30f, m1 = -1e30f, l0 = 0.f, l1 = 0.f;
    float O[8][4];
#pragma unroll
    for (int nt = 0; nt < 8; nt++)
#pragma unroll
        for (int j = 0; j < 4; j++) O[nt][j] = 0.f;

    for (int kc = 0; kc < GWIN; kc += 64) {
        __syncthreads();
        // load K,V chunks (64x64 each)
#pragma unroll
        for (int i = 0; i < 8; i++) {
            int lin = tid + i * 128;
            int r = lin >> 4, c4 = (lin & 15) * 4;
            const float* src = kv + (size_t)(b * GWIN + kc + r) * (2 * LDIM) + head * HEADDIM + c4;
            float4 kk = *(const float4*)&src[0];
            float4 vv = *(const float4*)&src[LDIM];
            uint4 tk, tv;
            tk.x = f2tf32(kk.x); tk.y = f2tf32(kk.y); tk.z = f2tf32(kk.z); tk.w = f2tf32(kk.w);
            tv.x = f2tf32(vv.x); tv.y = f2tf32(vv.y); tv.z = f2tf32(vv.z); tv.w = f2tf32(vv.w);
            *(uint4*)&sm[LA_K + r * 68 + c4] = tk;
            *(uint4*)&sm[LA_V + r * 72 + c4] = tv;
        }
        __syncthreads();

        // S = Q @ K^T  (warp: 16 q x 64 keys)
        float S[8][4];
#pragma unroll
        for (int nt = 0; nt < 8; nt++)
#pragma unroll
            for (int j = 0; j < 4; j++) S[nt][j] = 0.f;

#pragma unroll
        for (int k8 = 0; k8 < 8; k8++) {
            uint32_t af[4];
            int r = rbase + g;
            af[0] = smu[LA_Q + r * 68 + k8 * 8 + tig];
            af[1] = smu[LA_Q + (r + 8) * 68 + k8 * 8 + tig];
            af[2] = smu[LA_Q + r * 68 + k8 * 8 + tig + 4];
            af[3] = smu[LA_Q + (r + 8) * 68 + k8 * 8 + tig + 4];
#pragma unroll
            for (int nt = 0; nt < 8; nt++) {
                uint32_t bf[2];
                bf[0] = smu[LA_K + (nt * 8 + g) * 68 + k8 * 8 + tig];
                bf[1] = smu[LA_K + (nt * 8 + g) * 68 + k8 * 8 + tig + 4];
                mma_tf32(S[nt], af, bf);
            }
        }

        // online softmax (rows g and g+8 of this warp's 16)
        float mx0 = -1e30f, mx1 = -1e30f;
#pragma unroll
        for (int nt = 0; nt < 8; nt++) {
#pragma unroll
            for (int j = 0; j < 4; j++) S[nt][j] *= SCALE;
            mx0 = fmaxf(mx0, fmaxf(S[nt][0], S[nt][1]));
            mx1 = fmaxf(mx1, fmaxf(S[nt][2], S[nt][3]));
        }
        mx0 = fmaxf(mx0, __shfl_xor_sync(0xffffffffu, mx0, 1));
        mx0 = fmaxf(mx0, __shfl_xor_sync(0xffffffffu, mx0, 2));
        mx1 = fmaxf(mx1, __shfl_xor_sync(0xffffffffu, mx1, 1));
        mx1 = fmaxf(mx1, __shfl_xor_sync(0xffffffffu, mx1, 2));
        float mn0 = fmaxf(m0, mx0);
        float mn1 = fmaxf(m1, mx1);
        float rs0 = 0.f, rs1 = 0.f;
#pragma unroll
        for (int nt = 0; nt < 8; nt++) {
            float p0 = __expf(S[nt][0] - mn0);
            float p1 = __expf(S[nt][1] - mn0);
            float p2 = __expf(S[nt][2] - mn1);
            float p3 = __expf(S[nt][3] - mn1);
            rs0 += p0 + p1;
            rs1 += p2 + p3;
            int c = nt * 8 + tig * 2;
            uint32_t u0 = f2tf32(p0), u1 = f2tf32(p1), u2 = f2tf32(p2), u3 = f2tf32(p3);
            uint2 w0; w0.x = u0; w0.y = u1;
            uint2 w1; w1.x = u2; w1.y = u3;
            *(uint2*)&smu[LA_P + (rbase + g) * 68 + c] = w0;
            *(uint2*)&smu[LA_P + (rbase + g + 8) * 68 + c] = w1;
        }
        rs0 += __shfl_xor_sync(0xffffffffu, rs0, 1);
        rs0 += __shfl_xor_sync(0xffffffffu, rs0, 2);
        rs1 += __shfl_xor_sync(0xffffffffu, rs1, 1);
        rs1 += __shfl_xor_sync(0xffffffffu, rs1, 2);
        float a0 = __expf(m0 - mn0);
        float a1 = __expf(m1 - mn1);
        l0 = l0 * a0 + rs0;
        l1 = l1 * a1 + rs1;
        m0 = mn0; m1 = mn1;
#pragma unroll
        for (int nt = 0; nt < 8; nt++) {
            O[nt][0] *= a0; O[nt][1] *= a0;
            O[nt][2] *= a1; O[nt][3] *= a1;
        }
        __syncwarp();

        // O += P @ V  (A = P rows of this warp, B = V [key][d])
#pragma unroll
        for (int k8 = 0; k8 < 8; k8++) {
            uint32_t af[4];
            int r = rbase + g;
            af[0] = smu[LA_P + r * 68 + k8 * 8 + tig];
            af[1] = smu[LA_P + (r + 8) * 68 + k8 * 8 + tig];
            af[2] = smu[LA_P + r * 68 + k8 * 8 + tig + 4];
            af[3] = smu[LA_P + (r + 8) * 68 + k8 * 8 + tig + 4];
#pragma unroll
            for (int nt = 0; nt < 8; nt++) {
                uint32_t bf[2];
                bf[0] = smu[LA_V + (k8 * 8 + tig) * 72 + nt * 8 + g];
                bf[1] = smu[LA_V + (k8 * 8 + tig + 4) * 72 + nt * 8 + g];
                mma_tf32(O[nt], af, bf);
            }
        }
        __syncwarp();
    }

    float inv0 = 1.f / l0, inv1 = 1.f / l1;
#pragma unroll
    for (int nt = 0; nt < 8; nt++) {
        int c = head * HEADDIM + nt * 8 + tig * 2;
        float2 o0, o1;
        o0.x = O[nt][0] * inv0; o0.y = O[nt][1] * inv0;
        o1.x = O[nt][2] * inv1; o1.y = O[nt][3] * inv1;
        *(float2*)&lo[(size_t)(b * HW + q0 + rbase + g) * LDIM + c] = o0;
        *(float2*)&lo[(size_t)(b * HW + q0 + rbase + g + 8) * LDIM + c] = o1;
    }
}

// ---------------- 5) pack: [t][256] x2 -> out (B, 512, H, W) ----------------
__global__ void pack_kernel(const float* __restrict__ hifi, const float* __restrict__ lofi,
                            float* __restrict__ out) {
    __shared__ float tile[32][33];
    int t0 = blockIdx.x * 32;
    int c0g = blockIdx.y * 32;
    int tx = threadIdx.x, ty = threadIdx.y;
    const float* src;
    int c0;
    if (c0g < HDIM) { src = hifi; c0 = c0g; } else { src = lofi; c0 = c0g - HDIM; }
#pragma unroll
    for (int i = 0; i < 4; i++)
        tile[ty + i * 8][tx] = src[(size_t)(t0 + ty + i * 8) * 256 + c0 + tx];
    __syncthreads();
    int b = t0 / HW;
    int hw0 = t0 % HW;
#pragma unroll
    for (int i = 0; i < 4; i++)
        out[(size_t)(b * CDIM + c0g + ty + i * 8) * HW + hw0 + tx] = tile[tx][ty + i * 8];
}

// ---------------- launch ----------------
extern "C" void kernel_launch(void* const* d_in, const int* in_sizes, int n_in,
                              void* d_out, int out_size) {
    const float* x        = (const float*)d_in[0];
    const float* h_qkv_w  = (const float*)d_in[1];
    const float* h_proj_w = (const float*)d_in[2];
    const float* h_proj_b = (const float*)d_in[3];
    const float* l_q_w    = (const float*)d_in[4];
    const float* l_kv_w   = (const float*)d_in[5];
    const float* l_proj_w = (const float*)d_in[6];
    const float* l_proj_b = (const float*)d_in[7];
    float* out = (float*)d_out;

    float *p_xt, *p_pooled, *p_qkv, *p_hout, *p_hifi, *p_lq, *p_kv, *p_lo, *p_lofi;
    cudaGetSymbolAddress((void**)&p_xt, g_xt);
    cudaGetSymbolAddress((void**)&p_pooled, g_pooled);
    cudaGetSymbolAddress((void**)&p_qkv, g_qkv);
    cudaGetSymbolAddress((void**)&p_hout, g_hout);
    cudaGetSymbolAddress((void**)&p_hifi, g_hifi);
    cudaGetSymbolAddress((void**)&p_lq, g_lq);
    cudaGetSymbolAddress((void**)&p_kv, g_kv);
    cudaGetSymbolAddress((void**)&p_lo, g_lo);
    cudaGetSymbolAddress((void**)&p_lofi, g_lofi);

    transpose_x_kernel<<<dim3(HW / 32, CDIM / 32, BATCH), dim3(32, 8)>>>(x, p_xt);
    pool_kernel<<<BATCH * GWIN, 128>>>(p_xt, p_pooled);
    // qkv = xt @ h_qkv_w  [16384 x 768]
    tf32_gemm<false><<<dim3(768 / 128, TTOK / 128), 256>>>(p_xt, h_qkv_w, nullptr, p_qkv, TTOK, 768, CDIM);
    winattn_kernel<<<BATCH * GWIN, 128>>>(p_qkv, p_hout);
    // hifi = hout @ h_proj_w + b
    tf32_gemm<true><<<dim3(HDIM / 128, TTOK / 128), 256>>>(p_hout, h_proj_w, h_proj_b, p_hifi, TTOK, HDIM, HDIM);
    // lq = xt @ l_q_w
    tf32_gemm<false><<<dim3(LDIM / 128, TTOK / 128), 256>>>(p_xt, l_q_w, nullptr, p_lq, TTOK, LDIM, CDIM);
    // kv = pooled @ l_kv_w  [4096 x 512]
    tf32_gemm<false><<<dim3(512 / 128, (BATCH * GWIN) / 128), 256>>>(p_pooled, l_kv_w, nullptr, p_kv,
                                                                    BATCH * GWIN, 2 * LDIM, CDIM);
    // low-freq flash attention
    size_t la_smem = (size_t)LA_FLOATS * sizeof(float);  // 70656 B
    cudaFuncSetAttribute(lowattn_mma_kernel, cudaFuncAttributeMaxDynamicSharedMemorySize, (int)la_smem);
    lowattn_mma_kernel<<<dim3(HW / 64, BATCH * 4), 128, la_smem>>>(p_lq, p_kv, p_lo);
    // lofi = lo @ l_proj_w + b
    tf32_gemm<true><<<dim3(LDIM / 128, TTOK / 128), 256>>>(p_lo, l_proj_w, l_proj_b, p_lofi, TTOK, LDIM, LDIM);
    pack_kernel<<<dim3(TTOK / 32, CDIM / 32), dim3(32, 8)>>>(p_hifi, p_lofi, out);
}

// round 3
// speedup vs baseline: 3.1829x; 1.0662x over previous
#include <cuda_runtime.h>
#include <math.h>
#include <stdint.h>

// ---------------- problem constants ----------------
#define BATCH   4
#define CDIM    512
#define WSZ_    64
#define HW      4096
#define TTOK    16384
#define HEADDIM 64
#define HDIM    256
#define LDIM    256
#define GWIN    1024
#define SCALE   0.125f

// ---------------- scratch ----------------
__device__ float g_pooled[BATCH * CDIM * GWIN];   // [b][c][g]
__device__ float g_qkv[TTOK * 3 * HDIM];
__device__ float g_hout[TTOK * HDIM];
__device__ float g_lq[TTOK * LDIM];
__device__ float g_kv[BATCH * GWIN * 2 * LDIM];
__device__ float g_lo[TTOK * LDIM];

__device__ __forceinline__ uint32_t f2tf32(float x) {
    uint32_t r;
    asm("cvt.rna.tf32.f32 %0, %1;" : "=r"(r) : "f"(x));
    return r;
}

__device__ __forceinline__ void mma_tf32(float c[4], const uint32_t a[4], const uint32_t b[2]) {
    asm volatile(
        "mma.sync.aligned.m16n8k8.row.col.f32.tf32.tf32.f32 "
        "{%0,%1,%2,%3}, {%4,%5,%6,%7}, {%8,%9}, {%0,%1,%2,%3};\n"
        : "+f"(c[0]), "+f"(c[1]), "+f"(c[2]), "+f"(c[3])
        : "r"(a[0]), "r"(a[1]), "r"(a[2]), "r"(a[3]), "r"(b[0]), "r"(b[1]));
}

// ---------------- 1) 2x2 average pool directly from x -> pooled [b][c][g] ----------------
__global__ void pool_kernel(const float* __restrict__ x, float* __restrict__ pooled) {
    int bc = blockIdx.x;                      // b*512 + c
    const float* src = x + (size_t)bc * HW;
    float* dst = pooled + (size_t)bc * GWIN;
#pragma unroll
    for (int i = 0; i < 4; i++) {
        int g = threadIdx.x + i * 256;        // 0..1023
        int gy = g >> 5, gx = g & 31;
        float2 a = *(const float2*)&src[(2 * gy) * WSZ_ + 2 * gx];
        float2 b = *(const float2*)&src[(2 * gy + 1) * WSZ_ + 2 * gx];
        dst[g] = 0.25f * (a.x + a.y + b.x + b.y);
    }
}

// ---------------- tf32 GEMM, tile 128x128x32, 4 warps, warp tile 64x64 ----------------
// AT:  A is K-major "image" layout: A[(b*CDIM + k)*TPB + hw]  (token m = b*TPB + hw)
// !AT: A row-major [M][K]
// TOUT: write C transposed into (B, CDIM, H, W) at channel offset cbase
// smem: As 2x4608 | Bs 2x4352 = 17920 floats (71680 B); TOUT stage reuses it (128x132)
template <bool AT, bool HAS_BIAS, bool TOUT, int TPB>
__global__ void __launch_bounds__(128) tf32_gemm2(const float* __restrict__ A,
                                                  const float* __restrict__ B,
                                                  const float* __restrict__ bias,
                                                  float* __restrict__ C,
                                                  int N, int K, int cbase) {
    extern __shared__ float sm[];
    float* Asb[2] = { sm, sm + 4608 };
    float* Bsb[2] = { sm + 9216, sm + 9216 + 4352 };

    const int tid = threadIdx.x;
    const int warp = tid >> 5, lane = tid & 31;
    const int g = lane >> 2, tig = lane & 3;
    const int mw = (warp & 1) * 64, nw = (warp >> 1) * 64;
    const int m0 = blockIdx.y * 128, n0 = blockIdx.x * 128;
    const int bq = m0 / TPB, hw0 = m0 % TPB;
    const float* Ab = AT ? (A + ((size_t)bq * CDIM) * TPB + hw0) : A;

    float acc[4][8][4];
#pragma unroll
    for (int mt = 0; mt < 4; mt++)
#pragma unroll
        for (int nt = 0; nt < 8; nt++)
#pragma unroll
            for (int j = 0; j < 4; j++) acc[mt][nt][j] = 0.f;

    float4 stA[8], stB[8];

    // ---- LDG stage ----
    auto ldg = [&](int k0) {
#pragma unroll
        for (int i = 0; i < 8; i++) {
            int lin = tid + i * 128;
            if (AT) {
                int row = lin >> 5, col = (lin & 31) * 4;
                stA[i] = *(const float4*)&Ab[(size_t)(k0 + row) * TPB + col];
            } else {
                int m = lin >> 3, k4 = (lin & 7) * 4;
                stA[i] = *(const float4*)&A[(size_t)(m0 + m) * K + k0 + k4];
            }
            int kr = lin >> 5, n4 = (lin & 31) * 4;
            stB[i] = *(const float4*)&B[(size_t)(k0 + kr) * N + n0 + n4];
        }
    };
    // ---- cvt + STS ----
    auto sts = [&](int buf) {
        float* as = Asb[buf];
        float* bs = Bsb[buf];
#pragma unroll
        for (int i = 0; i < 8; i++) {
            int lin = tid + i * 128;
            uint4 t;
            t.x = f2tf32(stA[i].x); t.y = f2tf32(stA[i].y);
            t.z = f2tf32(stA[i].z); t.w = f2tf32(stA[i].w);
            if (AT) {
                int row = lin >> 5, col = (lin & 31) * 4;
                *(uint4*)&as[row * 136 + col] = t;     // [k][m], stride 136
            } else {
                int m = lin >> 3, k4 = (lin & 7) * 4;
                uint32_t* p = (uint32_t*)as;            // [m][k], stride 36
                p[m * 36 + k4 + 0] = t.x; p[m * 36 + k4 + 1] = t.y;
                p[m * 36 + k4 + 2] = t.z; p[m * 36 + k4 + 3] = t.w;
            }
            uint4 tb;
            tb.x = f2tf32(stB[i].x); tb.y = f2tf32(stB[i].y);
            tb.z = f2tf32(stB[i].z); tb.w = f2tf32(stB[i].w);
            int kr = lin >> 5, n4 = (lin & 31) * 4;
            *(uint4*)&bs[kr * 136 + n4] = tb;           // [k][n], stride 136
        }
    };

    const int nIter = K / 32;
    ldg(0);
    sts(0);
    __syncthreads();

    for (int it = 0; it < nIter; it++) {
        if (it + 1 < nIter) ldg((it + 1) * 32);
        const uint32_t* Asu = (const uint32_t*)Asb[it & 1];
        const uint32_t* Bsu = (const uint32_t*)Bsb[it & 1];
#pragma unroll
        for (int k8 = 0; k8 < 4; k8++) {
            uint32_t af[4][4], bf[8][2];
            int kk = k8 * 8 + tig;
#pragma unroll
            for (int mt = 0; mt < 4; mt++) {
                int r = mw + mt * 16 + g;
                if (AT) {
                    af[mt][0] = Asu[kk * 136 + r];
                    af[mt][1] = Asu[kk * 136 + r + 8];
                    af[mt][2] = Asu[(kk + 4) * 136 + r];
                    af[mt][3] = Asu[(kk + 4) * 136 + r + 8];
                } else {
                    af[mt][0] = Asu[r * 36 + kk];
                    af[mt][1] = Asu[(r + 8) * 36 + kk];
                    af[mt][2] = Asu[r * 36 + kk + 4];
                    af[mt][3] = Asu[(r + 8) * 36 + kk + 4];
                }
            }
#pragma unroll
            for (int nt = 0; nt < 8; nt++) {
                int c = nw + nt * 8 + g;
                bf[nt][0] = Bsu[kk * 136 + c];
                bf[nt][1] = Bsu[(kk + 4) * 136 + c];
            }
#pragma unroll
            for (int mt = 0; mt < 4; mt++)
#pragma unroll
                for (int nt = 0; nt < 8; nt++)
                    mma_tf32(acc[mt][nt], af[mt], bf[nt]);
        }
        if (it + 1 < nIter) sts((it + 1) & 1);
        __syncthreads();
    }

    if (!TOUT) {
#pragma unroll
        for (int mt = 0; mt < 4; mt++) {
            int r = m0 + mw + mt * 16 + g;
#pragma unroll
            for (int nt = 0; nt < 8; nt++) {
                int c = n0 + nw + nt * 8 + tig * 2;
                float2 o0, o1;
                o0.x = acc[mt][nt][0]; o0.y = acc[mt][nt][1];
                o1.x = acc[mt][nt][2]; o1.y = acc[mt][nt][3];
                *(float2*)&C[(size_t)r * N + c] = o0;
                *(float2*)&C[(size_t)(r + 8) * N + c] = o1;
            }
        }
    } else {
        // stage into sm [n][m], stride 132, then coalesced transposed writes
#pragma unroll
        for (int mt = 0; mt < 4; mt++)
#pragma unroll
            for (int nt = 0; nt < 8; nt++) {
                int cl = nw + nt * 8 + tig * 2;
                int rl = mw + mt * 16 + g;
                float b0 = 0.f, b1 = 0.f;
                if (HAS_BIAS) { b0 = bias[n0 + cl]; b1 = bias[n0 + cl + 1]; }
                sm[cl * 132 + rl]           = acc[mt][nt][0] + b0;
                sm[(cl + 1) * 132 + rl]     = acc[mt][nt][1] + b1;
                sm[cl * 132 + rl + 8]       = acc[mt][nt][2] + b0;
                sm[(cl + 1) * 132 + rl + 8] = acc[mt][nt][3] + b1;
            }
        __syncthreads();
#pragma unroll
        for (int rr = 0; rr < 32; rr++) {
            int n = warp * 32 + rr;
            float4 v = *(const float4*)&sm[n * 132 + lane * 4];
            *(float4*)&C[((size_t)(bq * CDIM + cbase + n0 + n)) * TPB + hw0 + lane * 4] = v;
        }
    }
}

// ---------------- window attention (float2 per lane) ----------------
__global__ void winattn_kernel(const float* __restrict__ qkv, float* __restrict__ hout) {
    int win = blockIdx.x;
    int b = win >> 10;
    int g = win & 1023;
    int gy = g >> 5, gx = g & 31;
    int head = threadIdx.x >> 5;
    int lane = threadIdx.x & 31;

    int tbase = b * HW + gy * 2 * WSZ_ + gx * 2;
    int t[4] = {tbase, tbase + 1, tbase + WSZ_, tbase + WSZ_ + 1};

    float2 q[4], k[4], v[4];
#pragma unroll
    for (int n = 0; n < 4; n++) {
        const float* row = qkv + (size_t)t[n] * (3 * HDIM) + head * HEADDIM + 2 * lane;
        q[n] = *(const float2*)&row[0];
        k[n] = *(const float2*)&row[HDIM];
        v[n] = *(const float2*)&row[2 * HDIM];
    }

    float s[4][4];
#pragma unroll
    for (int n = 0; n < 4; n++)
#pragma unroll
        for (int m = 0; m < 4; m++) s[n][m] = q[n].x * k[m].x + q[n].y * k[m].y;

#pragma unroll
    for (int o = 16; o > 0; o >>= 1)
#pragma unroll
        for (int n = 0; n < 4; n++)
#pragma unroll
            for (int m = 0; m < 4; m++) s[n][m] += __shfl_xor_sync(0xffffffffu, s[n][m], o);

#pragma unroll
    for (int n = 0; n < 4; n++) {
        float sv[4];
#pragma unroll
        for (int m = 0; m < 4; m++) sv[m] = s[n][m] * SCALE;
        float mx = fmaxf(fmaxf(sv[0], sv[1]), fmaxf(sv[2], sv[3]));
        float p[4], l = 0.f;
#pragma unroll
        for (int m = 0; m < 4; m++) { p[m] = __expf(sv[m] - mx); l += p[m]; }
        float inv = 1.f / l;
        float ox = 0.f, oy = 0.f;
#pragma unroll
        for (int m = 0; m < 4; m++) { ox += p[m] * v[m].x; oy += p[m] * v[m].y; }
        float2 o2; o2.x = ox * inv; o2.y = oy * inv;
        *(float2*)&hout[(size_t)t[n] * HDIM + head * HEADDIM + 2 * lane] = o2;
    }
}

// ---------------- low-freq flash attention, QTILE=128, 4 warps x 32 q-rows ----------------
// smem: Q 128x68 | K 64x68 | V 64x72 | P 128x68 = 26368 floats (105472 B)
#define LB_Q  0
#define LB_K  (128 * 68)
#define LB_V  (LB_K + 64 * 68)
#define LB_P  (LB_V + 64 * 72)
#define LB_FLOATS (LB_P + 128 * 68)

__global__ void __launch_bounds__(128) lowattn_mma_kernel(const float* __restrict__ lq,
                                                          const float* __restrict__ kv,
                                                          float* __restrict__ lo) {
    extern __shared__ float sm[];
    uint32_t* smu = (uint32_t*)sm;

    int q0 = blockIdx.x * 128;
    int bh = blockIdx.y;
    int b = bh >> 2, head = bh & 3;
    int tid = threadIdx.x;
    int warp = tid >> 5, lane = tid & 31;
    int g = lane >> 2, tig = lane & 3;
    int rbase = warp * 32;

    // load Q (128x64)
#pragma unroll
    for (int i = 0; i < 16; i++) {
        int lin = tid + i * 128;
        int r = lin >> 4, c4 = (lin & 15) * 4;
        float4 v = *(const float4*)&lq[(size_t)(b * HW + q0 + r) * LDIM + head * HEADDIM + c4];
        uint4 t;
        t.x = f2tf32(v.x); t.y = f2tf32(v.y); t.z = f2tf32(v.z); t.w = f2tf32(v.w);
        *(uint4*)&sm[LB_Q + r * 68 + c4] = t;
    }

    float m_[2][2], l_[2][2];
    float O[2][8][4];
#pragma unroll
    for (int mt = 0; mt < 2; mt++) {
        m_[mt][0] = -1e30f; m_[mt][1] = -1e30f;
        l_[mt][0] = 0.f;    l_[mt][1] = 0.f;
#pragma unroll
        for (int nt = 0; nt < 8; nt++)
#pragma unroll
            for (int j = 0; j < 4; j++) O[mt][nt][j] = 0.f;
    }

    for (int kc = 0; kc < GWIN; kc += 64) {
        __syncthreads();
#pragma unroll
        for (int i = 0; i < 8; i++) {
            int lin = tid + i * 128;
            int r = lin >> 4, c4 = (lin & 15) * 4;
            const float* src = kv + (size_t)(b * GWIN + kc + r) * (2 * LDIM) + head * HEADDIM + c4;
            float4 kk = *(const float4*)&src[0];
            float4 vv = *(const float4*)&src[LDIM];
            uint4 tk, tv;
            tk.x = f2tf32(kk.x); tk.y = f2tf32(kk.y); tk.z = f2tf32(kk.z); tk.w = f2tf32(kk.w);
            tv.x = f2tf32(vv.x); tv.y = f2tf32(vv.y); tv.z = f2tf32(vv.z); tv.w = f2tf32(vv.w);
            *(uint4*)&sm[LB_K + r * 68 + c4] = tk;
            *(uint4*)&sm[LB_V + r * 72 + c4] = tv;
        }
        __syncthreads();

        // S = Q @ K^T  (32 q x 64 keys per warp)
        float S[2][8][4];
#pragma unroll
        for (int mt = 0; mt < 2; mt++)
#pragma unroll
            for (int nt = 0; nt < 8; nt++)
#pragma unroll
                for (int j = 0; j < 4; j++) S[mt][nt][j] = 0.f;

#pragma unroll
        for (int k8 = 0; k8 < 8; k8++) {
            int kk = k8 * 8 + tig;
            uint32_t af[2][4], bf[8][2];
#pragma unroll
            for (int mt = 0; mt < 2; mt++) {
                int r = rbase + mt * 16 + g;
                af[mt][0] = smu[LB_Q + r * 68 + kk];
                af[mt][1] = smu[LB_Q + (r + 8) * 68 + kk];
                af[mt][2] = smu[LB_Q + r * 68 + kk + 4];
                af[mt][3] = smu[LB_Q + (r + 8) * 68 + kk + 4];
            }
#pragma unroll
            for (int nt = 0; nt < 8; nt++) {
                bf[nt][0] = smu[LB_K + (nt * 8 + g) * 68 + kk];
                bf[nt][1] = smu[LB_K + (nt * 8 + g) * 68 + kk + 4];
            }
#pragma unroll
            for (int mt = 0; mt < 2; mt++)
#pragma unroll
                for (int nt = 0; nt < 8; nt++)
                    mma_tf32(S[mt][nt], af[mt], bf[nt]);
        }

        // online softmax + P store (tf32)
#pragma unroll
        for (int mt = 0; mt < 2; mt++) {
            float mx0 = -1e30f, mx1 = -1e30f;
#pragma unroll
            for (int nt = 0; nt < 8; nt++) {
#pragma unroll
                for (int j = 0; j < 4; j++) S[mt][nt][j] *= SCALE;
                mx0 = fmaxf(mx0, fmaxf(S[mt][nt][0], S[mt][nt][1]));
                mx1 = fmaxf(mx1, fmaxf(S[mt][nt][2], S[mt][nt][3]));
            }
            mx0 = fmaxf(mx0, __shfl_xor_sync(0xffffffffu, mx0, 1));
            mx0 = fmaxf(mx0, __shfl_xor_sync(0xffffffffu, mx0, 2));
            mx1 = fmaxf(mx1, __shfl_xor_sync(0xffffffffu, mx1, 1));
            mx1 = fmaxf(mx1, __shfl_xor_sync(0xffffffffu, mx1, 2));
            float mn0 = fmaxf(m_[mt][0], mx0);
            float mn1 = fmaxf(m_[mt][1], mx1);
            float rs0 = 0.f, rs1 = 0.f;
            int r = rbase + mt * 16 + g;
#pragma unroll
            for (int nt = 0; nt < 8; nt++) {
                float p0 = __expf(S[mt][nt][0] - mn0);
                float p1 = __expf(S[mt][nt][1] - mn0);
                float p2 = __expf(S[mt][nt][2] - mn1);
                float p3 = __expf(S[mt][nt][3] - mn1);
                rs0 += p0 + p1;
                rs1 += p2 + p3;
                int c = nt * 8 + tig * 2;
                uint2 w0; w0.x = f2tf32(p0); w0.y = f2tf32(p1);
                uint2 w1; w1.x = f2tf32(p2); w1.y = f2tf32(p3);
                *(uint2*)&smu[LB_P + r * 68 + c] = w0;
                *(uint2*)&smu[LB_P + (r + 8) * 68 + c] = w1;
            }
            rs0 += __shfl_xor_sync(0xffffffffu, rs0, 1);
            rs0 += __shfl_xor_sync(0xffffffffu, rs0, 2);
            rs1 += __shfl_xor_sync(0xffffffffu, rs1, 1);
            rs1 += __shfl_xor_sync(0xffffffffu, rs1, 2);
            float a0 = __expf(m_[mt][0] - mn0);
            float a1 = __expf(m_[mt][1] - mn1);
            l_[mt][0] = l_[mt][0] * a0 + rs0;
            l_[mt][1] = l_[mt][1] * a1 + rs1;
            m_[mt][0] = mn0; m_[mt][1] = mn1;
#pragma unroll
            for (int nt = 0; nt < 8; nt++) {
                O[mt][nt][0] *= a0; O[mt][nt][1] *= a0;
                O[mt][nt][2] *= a1; O[mt][nt][3] *= a1;
            }
        }
        __syncwarp();

        // O += P @ V
#pragma unroll
        for (int k8 = 0; k8 < 8; k8++) {
            int kk = k8 * 8 + tig;
            uint32_t af[2][4], bf[8][2];
#pragma unroll
            for (int mt = 0; mt < 2; mt++) {
                int r = rbase + mt * 16 + g;
                af[mt][0] = smu[LB_P + r * 68 + kk];
                af[mt][1] = smu[LB_P + (r + 8) * 68 + kk];
                af[mt][2] = smu[LB_P + r * 68 + kk + 4];
                af[mt][3] = smu[LB_P + (r + 8) * 68 + kk + 4];
            }
#pragma unroll
            for (int nt = 0; nt < 8; nt++) {
                bf[nt][0] = smu[LB_V + kk * 72 + nt * 8 + g];
                bf[nt][1] = smu[LB_V + (kk + 4) * 72 + nt * 8 + g];
            }
#pragma unroll
            for (int mt = 0; mt < 2; mt++)
#pragma unroll
                for (int nt = 0; nt < 8; nt++)
                    mma_tf32(O[mt][nt], af[mt], bf[nt]);
        }
        __syncwarp();
    }

#pragma unroll
    for (int mt = 0; mt < 2; mt++) {
        float inv0 = 1.f / l_[mt][0];
        float inv1 = 1.f / l_[mt][1];
        int r = q0 + rbase + mt * 16 + g;
#pragma unroll
        for (int nt = 0; nt < 8; nt++) {
            int c = head * HEADDIM + nt * 8 + tig * 2;
            float2 o0, o1;
            o0.x = O[mt][nt][0] * inv0; o0.y = O[mt][nt][1] * inv0;
            o1.x = O[mt][nt][2] * inv1; o1.y = O[mt][nt][3] * inv1;
            *(float2*)&lo[(size_t)(b * HW + r) * LDIM + c] = o0;
            *(float2*)&lo[(size_t)(b * HW + r + 8) * LDIM + c] = o1;
        }
    }
}

// ---------------- launch ----------------
extern "C" void kernel_launch(void* const* d_in, const int* in_sizes, int n_in,
                              void* d_out, int out_size) {
    const float* x        = (const float*)d_in[0];
    const float* h_qkv_w  = (const float*)d_in[1];
    const float* h_proj_w = (const float*)d_in[2];
    const float* h_proj_b = (const float*)d_in[3];
    const float* l_q_w    = (const float*)d_in[4];
    const float* l_kv_w   = (const float*)d_in[5];
    const float* l_proj_w = (const float*)d_in[6];
    const float* l_proj_b = (const float*)d_in[7];
    float* out = (float*)d_out;

    float *p_pooled, *p_qkv, *p_hout, *p_lq, *p_kv, *p_lo;
    cudaGetSymbolAddress((void**)&p_pooled, g_pooled);
    cudaGetSymbolAddress((void**)&p_qkv, g_qkv);
    cudaGetSymbolAddress((void**)&p_hout, g_hout);
    cudaGetSymbolAddress((void**)&p_lq, g_lq);
    cudaGetSymbolAddress((void**)&p_kv, g_kv);
    cudaGetSymbolAddress((void**)&p_lo, g_lo);

    const int GEMM_SMEM = 17920 * 4;   // 71680 B
    cudaFuncSetAttribute(tf32_gemm2<true, false, false, HW>,
                         cudaFuncAttributeMaxDynamicSharedMemorySize, GEMM_SMEM);
    cudaFuncSetAttribute(tf32_gemm2<true, false, false, GWIN>,
                         cudaFuncAttributeMaxDynamicSharedMemorySize, GEMM_SMEM);
    cudaFuncSetAttribute(tf32_gemm2<false, true, true, HW>,
                         cudaFuncAttributeMaxDynamicSharedMemorySize, GEMM_SMEM);
    const int LA_SMEM = LB_FLOATS * 4; // 105472 B
    cudaFuncSetAttribute(lowattn_mma_kernel,
                         cudaFuncAttributeMaxDynamicSharedMemorySize, LA_SMEM);

    // 1) pool (from x)
    pool_kernel<<<BATCH * CDIM, 256>>>(x, p_pooled);
    // 2) qkv = x^T @ h_qkv_w  [16384 x 768]
    tf32_gemm2<true, false, false, HW><<<dim3(768 / 128, TTOK / 128), 128, GEMM_SMEM>>>(
        x, h_qkv_w, nullptr, p_qkv, 768, CDIM, 0);
    // 3) window attention
    winattn_kernel<<<BATCH * GWIN, 128>>>(p_qkv, p_hout);
    // 4) hifi = hout @ h_proj_w + b -> out channels [0,256)
    tf32_gemm2<false, true, true, HW><<<dim3(HDIM / 128, TTOK / 128), 128, GEMM_SMEM>>>(
        p_hout, h_proj_w, h_proj_b, out, HDIM, HDIM, 0);
    // 5) lq = x^T @ l_q_w
    tf32_gemm2<true, false, false, HW><<<dim3(LDIM / 128, TTOK / 128), 128, GEMM_SMEM>>>(
        x, l_q_w, nullptr, p_lq, LDIM, CDIM, 0);
    // 6) kv = pooled^T @ l_kv_w  [4096 x 512]
    tf32_gemm2<true, false, false, GWIN><<<dim3(512 / 128, (BATCH * GWIN) / 128), 128, GEMM_SMEM>>>(
        p_pooled, l_kv_w, nullptr, p_kv, 2 * LDIM, CDIM, 0);
    // 7) low-freq flash attention
    lowattn_mma_kernel<<<dim3(HW / 128, BATCH * 4), 128, LA_SMEM>>>(p_lq, p_kv, p_lo);
    // 8) lofi = lo @ l_proj_w + b -> out channels [256,512)
    tf32_gemm2<false, true, true, HW><<<dim3(LDIM / 128, TTOK / 128), 128, GEMM_SMEM>>>(
        p_lo, l_proj_w, l_proj_b, out, LDIM, LDIM, 256);
}